// round 2
// baseline (speedup 1.0000x reference)
#include <cuda_runtime.h>
#include <stdint.h>

#define BROWS 16384
#define GENES 19064
#define G4 (GENES / 4)          // 4766
#define NCHROM 23
#define NDROP 4
#define SCALE 5.75f             // 1 / (4/23)

// Set to 1 for jax_threefry_partitionable=True (default in JAX >= 0.5.0).
// If rel_err explodes, flip to 0 (legacy split/random_bits) next round.
#define PARTITIONABLE 1

__device__ unsigned      g_mask[BROWS];      // 23-bit drop mask per row
__device__ unsigned char g_chrom8[GENES];    // chrom id per gene, packed to bytes

// ---------------- threefry2x32 (exact JAX rounds) ----------------
__device__ __forceinline__ uint32_t rotl32(uint32_t x, int d) {
    return (x << d) | (x >> (32 - d));
}

__device__ __forceinline__ void threefry2x32(uint32_t k0, uint32_t k1,
                                             uint32_t x0, uint32_t x1,
                                             uint32_t& o0, uint32_t& o1) {
    uint32_t ks2 = k0 ^ k1 ^ 0x1BD11BDAu;
    x0 += k0; x1 += k1;
#define TF_RND(r) { x0 += x1; x1 = rotl32(x1, r); x1 ^= x0; }
    TF_RND(13) TF_RND(15) TF_RND(26) TF_RND(6)   x0 += k1;  x1 += ks2 + 1u;
    TF_RND(17) TF_RND(29) TF_RND(16) TF_RND(24)  x0 += ks2; x1 += k0  + 2u;
    TF_RND(13) TF_RND(15) TF_RND(26) TF_RND(6)   x0 += k0;  x1 += k1  + 3u;
    TF_RND(17) TF_RND(29) TF_RND(16) TF_RND(24)  x0 += k1;  x1 += ks2 + 4u;
    TF_RND(13) TF_RND(15) TF_RND(26) TF_RND(6)   x0 += ks2; x1 += k0  + 5u;
#undef TF_RND
    o0 = x0; o1 = x1;
}

#if !PARTITIONABLE
// legacy threefry_2x32(key, iota(num)) helper: concat[i] of split(key(42), BROWS)
__device__ __forceinline__ uint32_t legacy_split_word(uint32_t i) {
    uint32_t a, b;
    if (i < (uint32_t)BROWS) { threefry2x32(0u, 42u, i, i + BROWS, a, b); return a; }
    else                     { threefry2x32(0u, 42u, i - BROWS, i, a, b); return b; }
}
#endif

// ---------------- per-row mask + chrom byte-pack ----------------
__global__ void setup_kernel(const int* __restrict__ chrom_ids) {
    unsigned t = blockIdx.x * blockDim.x + threadIdx.x;

    if (t < GENES) g_chrom8[t] = (unsigned char)chrom_ids[t];

    if (t >= BROWS) return;

    uint32_t bits[NCHROM];
#if PARTITIONABLE
    // row key = tf(0,42, 0,b); subkey = tf(kb, 0,1); bits[j] = fold(tf(sk, 0,j))
    uint32_t kb0, kb1, sk0, sk1;
    threefry2x32(0u, 42u, 0u, t, kb0, kb1);
    threefry2x32(kb0, kb1, 0u, 1u, sk0, sk1);
#pragma unroll
    for (int j = 0; j < NCHROM; j++) {
        uint32_t a, b;
        threefry2x32(sk0, sk1, 0u, (uint32_t)j, a, b);
        bits[j] = a ^ b;
    }
#else
    // legacy: key_b = (concat[2b], concat[2b+1]); subkey from counts (0,2),(1,3);
    // bits = threefry_2x32(subkey, iota(23)) with odd-size zero pad.
    uint32_t kb0 = legacy_split_word(2u * t);
    uint32_t kb1 = legacy_split_word(2u * t + 1u);
    uint32_t a0, b0, a1, b1;
    threefry2x32(kb0, kb1, 0u, 2u, a0, b0);
    threefry2x32(kb0, kb1, 1u, 3u, a1, b1);
    uint32_t sk0 = b0, sk1 = b1;
#pragma unroll
    for (int j = 0; j < 12; j++) {
        uint32_t a, b;
        uint32_t c2 = (j < 11) ? (uint32_t)(12 + j) : 0u;   // pad word
        threefry2x32(sk0, sk1, (uint32_t)j, c2, a, b);
        bits[j] = a;
        if (j < 11) bits[12 + j] = b;
    }
#endif

    // stable selection of the NDROP smallest sort-keys (stable sort semantics:
    // strict < with ascending index scan => earliest index wins ties)
    unsigned drop = 0;
#pragma unroll
    for (int s = 0; s < NDROP; s++) {
        int best = -1;
#pragma unroll
        for (int c = 0; c < NCHROM; c++) {
            if ((drop >> c) & 1u) continue;
            if (best < 0 || bits[c] < bits[best]) best = c;
        }
        drop |= 1u << best;
    }
    g_mask[t] = drop;
}

// ---------------- streaming apply: out = x * keep * 5.75 ----------------
__global__ void __launch_bounds__(256) apply_kernel(const float4* __restrict__ x,
                                                    float4* __restrict__ out) {
    unsigned i = blockIdx.x * blockDim.x + threadIdx.x;   // < B*G/4 (exact launch)
    unsigned b  = i / G4;
    unsigned g4 = i - b * G4;

    unsigned m  = g_mask[b];
    unsigned c4 = *reinterpret_cast<const unsigned*>(&g_chrom8[g4 * 4u]);

    float4 v = x[i];
    v.x = ((m >> ( c4        & 0xFFu)) & 1u) ? 0.f : v.x * SCALE;
    v.y = ((m >> ((c4 >> 8)  & 0xFFu)) & 1u) ? 0.f : v.y * SCALE;
    v.z = ((m >> ((c4 >> 16) & 0xFFu)) & 1u) ? 0.f : v.z * SCALE;
    v.w = ((m >> ((c4 >> 24) & 0xFFu)) & 1u) ? 0.f : v.w * SCALE;
    out[i] = v;
}

extern "C" void kernel_launch(void* const* d_in, const int* in_sizes, int n_in,
                              void* d_out, int out_size) {
    const float* x         = (const float*)d_in[0];
    const int*   chrom_ids = (const int*)d_in[1];
    float*       out       = (float*)d_out;

    // setup: covers max(BROWS, GENES) threads
    int setup_threads = GENES > BROWS ? GENES : BROWS;
    setup_kernel<<<(setup_threads + 255) / 256, 256>>>(chrom_ids);

    // apply: B*G/4 float4 elements, exactly divisible by 256
    unsigned n4 = (unsigned)BROWS * (unsigned)G4;   // 78,086,656
    apply_kernel<<<n4 / 256, 256>>>((const float4*)x, (float4*)out);
}

// round 3
// speedup vs baseline: 1.0477x; 1.0477x over previous
#include <cuda_runtime.h>
#include <stdint.h>

#define BROWS 16384
#define GENES 19064
#define G4 (GENES / 4)          // 4766
#define NCHROM 23
#define NDROP 4
#define SCALE 5.75f             // 1 / (4/23)
#define VEC 4                   // float4 per thread in apply

__device__ unsigned      g_mask[BROWS];      // 23-bit drop mask per row
__device__ unsigned char g_chrom8[GENES];    // chrom id per gene, packed to bytes

// ---------------- threefry2x32 (exact JAX rounds, partitionable path) ----------------
__device__ __forceinline__ uint32_t rotl32(uint32_t x, int d) {
    return (x << d) | (x >> (32 - d));
}

__device__ __forceinline__ void threefry2x32(uint32_t k0, uint32_t k1,
                                             uint32_t x0, uint32_t x1,
                                             uint32_t& o0, uint32_t& o1) {
    uint32_t ks2 = k0 ^ k1 ^ 0x1BD11BDAu;
    x0 += k0; x1 += k1;
#define TF_RND(r) { x0 += x1; x1 = rotl32(x1, r); x1 ^= x0; }
    TF_RND(13) TF_RND(15) TF_RND(26) TF_RND(6)   x0 += k1;  x1 += ks2 + 1u;
    TF_RND(17) TF_RND(29) TF_RND(16) TF_RND(24)  x0 += ks2; x1 += k0  + 2u;
    TF_RND(13) TF_RND(15) TF_RND(26) TF_RND(6)   x0 += k0;  x1 += k1  + 3u;
    TF_RND(17) TF_RND(29) TF_RND(16) TF_RND(24)  x0 += k1;  x1 += ks2 + 4u;
    TF_RND(13) TF_RND(15) TF_RND(26) TF_RND(6)   x0 += ks2; x1 += k0  + 5u;
#undef TF_RND
    o0 = x0; o1 = x1;
}

// ---------------- per-row mask + chrom byte-pack ----------------
__global__ void setup_kernel(const int* __restrict__ chrom_ids) {
    unsigned t = blockIdx.x * blockDim.x + threadIdx.x;

    if (t < GENES) g_chrom8[t] = (unsigned char)chrom_ids[t];

    if (t >= BROWS) return;

    // row key = tf(0,42, 0,b); subkey = tf(kb, 0,1); bits[j] = fold(tf(sk, 0,j))
    uint32_t kb0, kb1, sk0, sk1;
    threefry2x32(0u, 42u, 0u, t, kb0, kb1);
    threefry2x32(kb0, kb1, 0u, 1u, sk0, sk1);

    uint32_t bits[NCHROM];
#pragma unroll
    for (int j = 0; j < NCHROM; j++) {
        uint32_t a, b;
        threefry2x32(sk0, sk1, 0u, (uint32_t)j, a, b);
        bits[j] = a ^ b;
    }

    // stable selection of the NDROP smallest sort-keys (ties -> lowest index)
    unsigned drop = 0;
#pragma unroll
    for (int s = 0; s < NDROP; s++) {
        int best = -1;
#pragma unroll
        for (int c = 0; c < NCHROM; c++) {
            if ((drop >> c) & 1u) continue;
            if (best < 0 || bits[c] < bits[best]) best = c;
        }
        drop |= 1u << best;
    }
    g_mask[t] = drop;
}

// ---------------- streaming apply: out = x * keep * 5.75 ----------------
// Each thread handles VEC float4s, loads front-batched for MLP, streaming
// cache hints (no reuse on x/out).
__global__ void __launch_bounds__(256) apply_kernel(const float4* __restrict__ x,
                                                    float4* __restrict__ out) {
    unsigned base = blockIdx.x * (256u * VEC) + threadIdx.x;

    float4   v[VEC];
    unsigned idx[VEC];
#pragma unroll
    for (int k = 0; k < VEC; k++) {
        idx[k] = base + (unsigned)k * 256u;
        v[k]   = __ldcs(&x[idx[k]]);
    }

#pragma unroll
    for (int k = 0; k < VEC; k++) {
        unsigned i  = idx[k];
        unsigned b  = i / G4;
        unsigned g4 = i - b * G4;

        unsigned m  = g_mask[b];
        unsigned c4 = *reinterpret_cast<const unsigned*>(&g_chrom8[g4 * 4u]);

        float4 w = v[k];
        w.x = ((m >> ( c4        & 0xFFu)) & 1u) ? 0.f : w.x * SCALE;
        w.y = ((m >> ((c4 >> 8)  & 0xFFu)) & 1u) ? 0.f : w.y * SCALE;
        w.z = ((m >> ((c4 >> 16) & 0xFFu)) & 1u) ? 0.f : w.z * SCALE;
        w.w = ((m >> ((c4 >> 24) & 0xFFu)) & 1u) ? 0.f : w.w * SCALE;
        __stcs(&out[i], w);
    }
}

extern "C" void kernel_launch(void* const* d_in, const int* in_sizes, int n_in,
                              void* d_out, int out_size) {
    const float* x         = (const float*)d_in[0];
    const int*   chrom_ids = (const int*)d_in[1];
    float*       out       = (float*)d_out;

    // setup: covers max(BROWS, GENES) threads
    int setup_threads = GENES > BROWS ? GENES : BROWS;
    setup_kernel<<<(setup_threads + 255) / 256, 256>>>(chrom_ids);

    // apply: B*G/4 float4 elements = 78,086,144, divisible by 256*VEC=1024
    unsigned n4 = (unsigned)BROWS * (unsigned)G4;
    apply_kernel<<<n4 / (256u * VEC), 256>>>((const float4*)x, (float4*)out);
}